// round 1
// baseline (speedup 1.0000x reference)
#include <cuda_runtime.h>
#include <math.h>

#define BATCH   2
#define SEQ     1024
#define DMODEL  1024
#define NLAYER  4
#define VOCAB   32000
#define DSTATE  16
#define DCONV   4
#define DINNER  2048
#define DTRANK  64
#define TTOK    (BATCH*SEQ)     // 2048 tokens
#define XDBL_W  (DTRANK + 2*DSTATE)  // 96

// -------- scratch (device globals: allocation-free) --------
__device__ float g_h   [TTOK*DMODEL];      // residual stream
__device__ float g_xn  [TTOK*DMODEL];      // rmsnorm output
__device__ float g_xz  [TTOK*2*DINNER];    // in_proj output (xi | z)
__device__ float g_xc  [TTOK*DINNER];      // conv+silu output
__device__ float g_xdbl[TTOK*XDBL_W];      // x_proj output (dtr | B | C)
__device__ float g_dt  [TTOK*DINNER];      // softplus(dt)
__device__ float g_y   [TTOK*DINNER];      // scan output

// ----------------------------------------------------------
// embedding gather: one block per token, 256 threads x float4
// ----------------------------------------------------------
__global__ void embed_k(const int* __restrict__ tok,
                        const float* __restrict__ emb,
                        float* __restrict__ out)
{
    int t = blockIdx.x;
    int row = tok[t];
    const float4* src = (const float4*)(emb + (size_t)row * DMODEL);
    float4* dst = (float4*)(out + (size_t)t * DMODEL);
    dst[threadIdx.x] = src[threadIdx.x];
}

// ----------------------------------------------------------
// rmsnorm: one block per token (256 threads, D=1024)
// ----------------------------------------------------------
__global__ void rmsnorm_k(const float* __restrict__ x,
                          const float* __restrict__ w,
                          float* __restrict__ out)
{
    int t = blockIdx.x;
    int tid = threadIdx.x;
    const float4* xr = (const float4*)(x + (size_t)t * DMODEL);
    float4 v = xr[tid];
    float ss = v.x*v.x + v.y*v.y + v.z*v.z + v.w*v.w;

    __shared__ float sbuf[8];
    #pragma unroll
    for (int o = 16; o; o >>= 1) ss += __shfl_xor_sync(0xffffffffu, ss, o);
    int warp = tid >> 5, lane = tid & 31;
    if (lane == 0) sbuf[warp] = ss;
    __syncthreads();
    if (warp == 0) {
        float s2 = (lane < 8) ? sbuf[lane] : 0.f;
        #pragma unroll
        for (int o = 4; o; o >>= 1) s2 += __shfl_xor_sync(0xffffffffu, s2, o);
        if (lane == 0) sbuf[0] = rsqrtf(s2 * (1.0f / DMODEL) + 1e-5f);
    }
    __syncthreads();
    float r = sbuf[0];
    float4 wv = ((const float4*)w)[tid];
    float4 o4 = make_float4(v.x*r*wv.x, v.y*r*wv.y, v.z*r*wv.z, v.w*r*wv.w);
    ((float4*)(out + (size_t)t * DMODEL))[tid] = o4;
}

// ----------------------------------------------------------
// SGEMM (NT): C[T,N] = A[T,K] * W[N,K]^T, 128x128x8 tile, 8x8/thread
// EPI: 0=store, 1=accumulate into C, 2=softplus(acc + bias[col])
// ----------------------------------------------------------
#define BM 128
#define BN 128
#define BKK 8
#define TM 8
#define TN 8

template<int EPI>
__global__ __launch_bounds__(256)
void sgemm_nt(const float* __restrict__ A, int lda,
              const float* __restrict__ W, int ldw,
              float* __restrict__ C, int ldc,
              const float* __restrict__ bias,
              int T, int N, int K)
{
    __shared__ float As[BKK][BM];
    __shared__ float Ws[BKK][BN];

    int tid = threadIdx.x;
    int tileM = blockIdx.y * BM;
    int tileN = blockIdx.x * BN;

    int lrow = tid >> 1;          // 0..127
    int lcol = (tid & 1) * 4;     // 0 or 4
    int tx = tid & 15, ty = tid >> 4;

    float acc[TM][TN];
    #pragma unroll
    for (int m = 0; m < TM; m++)
        #pragma unroll
        for (int n = 0; n < TN; n++) acc[m][n] = 0.f;

    for (int k0 = 0; k0 < K; k0 += BKK) {
        float4 av = *(const float4*)(A + (size_t)(tileM + lrow) * lda + k0 + lcol);
        As[lcol+0][lrow] = av.x; As[lcol+1][lrow] = av.y;
        As[lcol+2][lrow] = av.z; As[lcol+3][lrow] = av.w;

        int wrow = tileN + lrow;
        float4 wv = make_float4(0.f, 0.f, 0.f, 0.f);
        if (wrow < N) wv = *(const float4*)(W + (size_t)wrow * ldw + k0 + lcol);
        Ws[lcol+0][lrow] = wv.x; Ws[lcol+1][lrow] = wv.y;
        Ws[lcol+2][lrow] = wv.z; Ws[lcol+3][lrow] = wv.w;

        __syncthreads();
        #pragma unroll
        for (int k = 0; k < BKK; k++) {
            float4 a0 = *(const float4*)&As[k][ty*TM];
            float4 a1 = *(const float4*)&As[k][ty*TM+4];
            float4 b0 = *(const float4*)&Ws[k][tx*TN];
            float4 b1 = *(const float4*)&Ws[k][tx*TN+4];
            float ra[TM] = {a0.x,a0.y,a0.z,a0.w,a1.x,a1.y,a1.z,a1.w};
            float rb[TN] = {b0.x,b0.y,b0.z,b0.w,b1.x,b1.y,b1.z,b1.w};
            #pragma unroll
            for (int m = 0; m < TM; m++)
                #pragma unroll
                for (int n = 0; n < TN; n++)
                    acc[m][n] += ra[m] * rb[n];
        }
        __syncthreads();
    }

    #pragma unroll
    for (int m = 0; m < TM; m++) {
        int row = tileM + ty*TM + m;
        if (row >= T) continue;
        #pragma unroll
        for (int n = 0; n < TN; n++) {
            int col = tileN + tx*TN + n;
            if (col >= N) continue;
            float v = acc[m][n];
            size_t ci = (size_t)row * ldc + col;
            if (EPI == 1) {
                C[ci] += v;
            } else if (EPI == 2) {
                v += bias[col];
                v = (v > 20.f) ? v : log1pf(expf(v));
                C[ci] = v;
            } else {
                C[ci] = v;
            }
        }
    }
}

// ----------------------------------------------------------
// depthwise causal conv (width 4) + bias + silu
// xi = xz[:, 0:DINNER] (row stride 2*DINNER)
// ----------------------------------------------------------
__global__ void conv_silu_k(const float* __restrict__ xz,
                            const float* __restrict__ cw,
                            const float* __restrict__ cb,
                            float* __restrict__ xc)
{
    int idx = blockIdx.x * blockDim.x + threadIdx.x;
    if (idx >= TTOK * DINNER) return;
    int c = idx % DINNER;
    int t = idx / DINNER;
    int l = t % SEQ;

    float4 w4 = *(const float4*)(cw + c * 4);
    const size_t str = 2 * DINNER;
    float acc = cb[c];
    if (l >= 3) acc += w4.x * xz[(size_t)(t-3)*str + c];
    if (l >= 2) acc += w4.y * xz[(size_t)(t-2)*str + c];
    if (l >= 1) acc += w4.z * xz[(size_t)(t-1)*str + c];
    acc += w4.w * xz[(size_t)t*str + c];
    // silu
    float s = 1.f / (1.f + expf(-acc));
    xc[idx] = acc * s;
}

// ----------------------------------------------------------
// selective scan: 1 thread per (channel, state); 16-lane groups
// per channel; y reduced via shuffles; epilogue fuses D-skip + silu(z)
// grid: 256 blocks x 256 threads  (16 channels x 16 states / block)
// ----------------------------------------------------------
__global__ __launch_bounds__(256)
void scan_k(const float* __restrict__ xdbl,
            const float* __restrict__ dt,
            const float* __restrict__ xc,
            const float* __restrict__ xz,
            const float* __restrict__ A_log,
            const float* __restrict__ Dsk,
            float* __restrict__ y)
{
    int s = threadIdx.x & 15;
    int c = ((blockIdx.x & 127) << 4) + (threadIdx.x >> 4);
    int b = blockIdx.x >> 7;

    float A = -expf(A_log[(size_t)c * DSTATE + s]);
    float dval = Dsk[c];
    bool lane0 = (s == 0);
    float h = 0.f;

    int tbase = b * SEQ;
    for (int l = 0; l < SEQ; l++) {
        int t = tbase + l;
        float dtv = dt[(size_t)t * DINNER + c];
        float xv  = xc[(size_t)t * DINNER + c];
        float Bv  = xdbl[(size_t)t * XDBL_W + DTRANK + s];
        float Cv  = xdbl[(size_t)t * XDBL_W + DTRANK + DSTATE + s];

        float dA = __expf(dtv * A);
        h = dA * h + (dtv * xv) * Bv;
        float p = h * Cv;
        p += __shfl_xor_sync(0xffffffffu, p, 8);
        p += __shfl_xor_sync(0xffffffffu, p, 4);
        p += __shfl_xor_sync(0xffffffffu, p, 2);
        p += __shfl_xor_sync(0xffffffffu, p, 1);
        if (lane0) {
            float z = xz[(size_t)t * (2*DINNER) + DINNER + c];
            float sg = 1.f / (1.f + __expf(-z));
            y[(size_t)t * DINNER + c] = (p + dval * xv) * (z * sg);
        }
    }
}

// ----------------------------------------------------------
extern "C" void kernel_launch(void* const* d_in, const int* in_sizes, int n_in,
                              void* d_out, int out_size)
{
    const int*   tokens       = (const int*)  d_in[0];
    const float* embed        = (const float*)d_in[1];
    const float* norm_w       = (const float*)d_in[2];
    const float* in_proj_w    = (const float*)d_in[3];
    const float* conv_w       = (const float*)d_in[4];
    const float* conv_b       = (const float*)d_in[5];
    const float* x_proj_w     = (const float*)d_in[6];
    const float* dt_w         = (const float*)d_in[7];
    const float* dt_b         = (const float*)d_in[8];
    const float* A_log        = (const float*)d_in[9];
    const float* D_skip       = (const float*)d_in[10];
    const float* out_proj_w   = (const float*)d_in[11];
    const float* final_norm_w = (const float*)d_in[12];
    float* out = (float*)d_out;

    float *h, *xn, *xz, *xc, *xdbl, *dts, *y;
    cudaGetSymbolAddress((void**)&h,    g_h);
    cudaGetSymbolAddress((void**)&xn,   g_xn);
    cudaGetSymbolAddress((void**)&xz,   g_xz);
    cudaGetSymbolAddress((void**)&xc,   g_xc);
    cudaGetSymbolAddress((void**)&xdbl, g_xdbl);
    cudaGetSymbolAddress((void**)&dts,  g_dt);
    cudaGetSymbolAddress((void**)&y,    g_y);

    embed_k<<<TTOK, 256>>>(tokens, embed, h);

    for (int L = 0; L < NLAYER; L++) {
        rmsnorm_k<<<TTOK, 256>>>(h, norm_w + (size_t)L * DMODEL, xn);

        // in_proj: [2048,1024] x [4096,1024]^T -> [2048,4096]
        sgemm_nt<0><<<dim3(2*DINNER/BN, TTOK/BM), 256>>>(
            xn, DMODEL,
            in_proj_w + (size_t)L * 2*DINNER*DMODEL, DMODEL,
            xz, 2*DINNER, nullptr, TTOK, 2*DINNER, DMODEL);

        conv_silu_k<<<(TTOK*DINNER + 255)/256, 256>>>(
            xz, conv_w + (size_t)L * DINNER*DCONV, conv_b + (size_t)L * DINNER, xc);

        // x_proj: [2048,2048] x [96,2048]^T -> [2048,96]
        sgemm_nt<0><<<dim3(1, TTOK/BM), 256>>>(
            xc, DINNER,
            x_proj_w + (size_t)L * XDBL_W*DINNER, DINNER,
            xdbl, XDBL_W, nullptr, TTOK, XDBL_W, DINNER);

        // dt: softplus([2048,64] x [2048,64]^T + dt_b) -> [2048,2048]
        sgemm_nt<2><<<dim3(DINNER/BN, TTOK/BM), 256>>>(
            xdbl, XDBL_W,
            dt_w + (size_t)L * DINNER*DTRANK, DTRANK,
            dts, DINNER, dt_b + (size_t)L * DINNER, TTOK, DINNER, DTRANK);

        scan_k<<<256, 256>>>(xdbl, dts, xc, xz,
                             A_log + (size_t)L * DINNER*DSTATE,
                             D_skip + (size_t)L * DINNER, y);

        // out_proj (accumulate residual): [2048,2048] x [1024,2048]^T += h
        sgemm_nt<1><<<dim3(DMODEL/BN, TTOK/BM), 256>>>(
            y, DINNER,
            out_proj_w + (size_t)L * DMODEL*DINNER, DINNER,
            h, DMODEL, nullptr, TTOK, DMODEL, DINNER);
    }

    rmsnorm_k<<<TTOK, 256>>>(h, final_norm_w, xn);

    // logits: [2048,1024] x [32000,1024]^T -> [2048,32000]
    sgemm_nt<0><<<dim3((VOCAB + BN - 1)/BN, TTOK/BM), 256>>>(
        xn, DMODEL, embed, DMODEL, out, VOCAB, nullptr, TTOK, VOCAB, DMODEL);
}

// round 2
// speedup vs baseline: 1.9867x; 1.9867x over previous
#include <cuda_runtime.h>
#include <math.h>
#include <stdint.h>

#define BATCH   2
#define SEQ     1024
#define DMODEL  1024
#define NLAYER  4
#define VOCAB   32000
#define DSTATE  16
#define DCONV   4
#define DINNER  2048
#define DTRANK  64
#define TTOK    (BATCH*SEQ)
#define XDBL_W  (DTRANK + 2*DSTATE)   // 96

// -------- scratch (device globals: allocation-free) --------
__device__ float g_h   [TTOK*DMODEL];
__device__ float g_xn  [TTOK*DMODEL];
__device__ float g_xz  [TTOK*2*DINNER];
__device__ float g_xc  [TTOK*DINNER];
__device__ float g_xdbl[TTOK*XDBL_W];
__device__ float g_dt  [TTOK*DINNER];
__device__ float g_y   [TTOK*DINNER];

// ----------------------------------------------------------
__global__ void embed_k(const int* __restrict__ tok,
                        const float* __restrict__ emb,
                        float* __restrict__ out)
{
    int t = blockIdx.x;
    int row = tok[t];
    const float4* src = (const float4*)(emb + (size_t)row * DMODEL);
    float4* dst = (float4*)(out + (size_t)t * DMODEL);
    dst[threadIdx.x] = src[threadIdx.x];
}

// ----------------------------------------------------------
__global__ void rmsnorm_k(const float* __restrict__ x,
                          const float* __restrict__ w,
                          float* __restrict__ out)
{
    int t = blockIdx.x;
    int tid = threadIdx.x;
    const float4* xr = (const float4*)(x + (size_t)t * DMODEL);
    float4 v = xr[tid];
    float ss = v.x*v.x + v.y*v.y + v.z*v.z + v.w*v.w;

    __shared__ float sbuf[8];
    #pragma unroll
    for (int o = 16; o; o >>= 1) ss += __shfl_xor_sync(0xffffffffu, ss, o);
    int warp = tid >> 5, lane = tid & 31;
    if (lane == 0) sbuf[warp] = ss;
    __syncthreads();
    if (warp == 0) {
        float s2 = (lane < 8) ? sbuf[lane] : 0.f;
        #pragma unroll
        for (int o = 4; o; o >>= 1) s2 += __shfl_xor_sync(0xffffffffu, s2, o);
        if (lane == 0) sbuf[0] = rsqrtf(s2 * (1.0f / DMODEL) + 1e-5f);
    }
    __syncthreads();
    float r = sbuf[0];
    float4 wv = ((const float4*)w)[tid];
    float4 o4 = make_float4(v.x*r*wv.x, v.y*r*wv.y, v.z*r*wv.z, v.w*r*wv.w);
    ((float4*)(out + (size_t)t * DMODEL))[tid] = o4;
}

// ----------------------------------------------------------
// TF32 tensor-core GEMM (NT): C[T,N] = A[T,K] * W[N,K]^T
// 128x128x32 CTA tile, 8 warps x (64x32), mma.m16n8k8.tf32,
// cp.async 2-stage pipeline. EPI: 0=store 1=accum 2=softplus+bias
// ----------------------------------------------------------
#define GBM 128
#define GBN 128
#define GBK 32
#define PADK 36          // 36 mod 32 == 4 -> conflict-free frag reads
#define TILE_F (GBM*PADK)
#define SMEM_BYTES (4*TILE_F*4)   // 2 stages x (A+B) = 73728 B

__device__ __forceinline__ uint32_t f2tf(float x) {
    uint32_t r;
    asm("cvt.rna.tf32.f32 %0, %1;" : "=r"(r) : "f"(x));
    return r;
}
__device__ __forceinline__ void cp16(uint32_t dst, const void* src, int srcBytes) {
    asm volatile("cp.async.cg.shared.global [%0], [%1], 16, %2;"
                 :: "r"(dst), "l"(src), "r"(srcBytes));
}
__device__ __forceinline__ void cp_commit() {
    asm volatile("cp.async.commit_group;");
}
template<int N> __device__ __forceinline__ void cp_wait() {
    asm volatile("cp.async.wait_group %0;" :: "n"(N));
}

template<int EPI>
__global__ __launch_bounds__(256, 1)
void tf32gemm(const float* __restrict__ A, int lda,
              const float* __restrict__ W, int ldw,
              float* __restrict__ C, int ldc,
              const float* __restrict__ bias,
              int T, int N, int K)
{
    extern __shared__ float smem[];
    // layout: As0 | As1 | Bs0 | Bs1
    float* AsBase = smem;
    float* BsBase = smem + 2*TILE_F;

    int tid  = threadIdx.x;
    int lane = tid & 31;
    int warp = tid >> 5;
    int wm = warp & 1;        // 0..1  -> 64-row half
    int wn = warp >> 1;       // 0..3  -> 32-col quarter
    int g  = lane >> 2;       // 0..7
    int t4 = lane & 3;        // 0..3

    int tileM = blockIdx.y * GBM;
    int tileN = blockIdx.x * GBN;

    float acc[4][4][4];
    #pragma unroll
    for (int mi = 0; mi < 4; mi++)
        #pragma unroll
        for (int ni = 0; ni < 4; ni++)
            #pragma unroll
            for (int e = 0; e < 4; e++) acc[mi][ni][e] = 0.f;

    uint32_t asmem = (uint32_t)__cvta_generic_to_shared(AsBase);
    uint32_t bsmem = (uint32_t)__cvta_generic_to_shared(BsBase);

    int iters = K / GBK;

    // ---- tile loader: 256 threads x 4 tasks each for A and B ----
    auto load_stage = [&](int s, int k0) {
        #pragma unroll
        for (int i = 0; i < 4; i++) {
            int task = tid + i*256;
            int row  = task >> 3;
            int c4   = (task & 7) * 4;
            uint32_t da = asmem + (uint32_t)((s*TILE_F + row*PADK + c4) * 4);
            cp16(da, A + (size_t)(tileM + row) * lda + k0 + c4, 16);

            int wrow = tileN + row;
            uint32_t db = bsmem + (uint32_t)((s*TILE_F + row*PADK + c4) * 4);
            const float* bsrc = W + (size_t)(wrow < N ? wrow : 0) * ldw + k0 + c4;
            cp16(db, bsrc, wrow < N ? 16 : 0);
        }
    };

    load_stage(0, 0);
    cp_commit();

    for (int it = 0; it < iters; it++) {
        int s = it & 1;
        if (it + 1 < iters) {
            load_stage((it + 1) & 1, (it + 1) * GBK);
            cp_commit();
            cp_wait<1>();
        } else {
            cp_wait<0>();
        }
        __syncthreads();

        const float* As = AsBase + s*TILE_F;
        const float* Bs = BsBase + s*TILE_F;

        #pragma unroll
        for (int ks = 0; ks < 4; ks++) {
            uint32_t ra[4][4], rb[4][2];
            #pragma unroll
            for (int mi = 0; mi < 4; mi++) {
                const float* ap = As + (wm*64 + mi*16 + g) * PADK + ks*8 + t4;
                ra[mi][0] = f2tf(ap[0]);
                ra[mi][1] = f2tf(ap[8*PADK]);
                ra[mi][2] = f2tf(ap[4]);
                ra[mi][3] = f2tf(ap[8*PADK + 4]);
            }
            #pragma unroll
            for (int ni = 0; ni < 4; ni++) {
                const float* bp = Bs + (wn*32 + ni*8 + g) * PADK + ks*8 + t4;
                rb[ni][0] = f2tf(bp[0]);
                rb[ni][1] = f2tf(bp[4]);
            }
            #pragma unroll
            for (int mi = 0; mi < 4; mi++)
                #pragma unroll
                for (int ni = 0; ni < 4; ni++) {
                    asm volatile(
                        "mma.sync.aligned.m16n8k8.row.col.f32.tf32.tf32.f32 "
                        "{%0,%1,%2,%3}, {%4,%5,%6,%7}, {%8,%9}, {%0,%1,%2,%3};\n"
                        : "+f"(acc[mi][ni][0]), "+f"(acc[mi][ni][1]),
                          "+f"(acc[mi][ni][2]), "+f"(acc[mi][ni][3])
                        : "r"(ra[mi][0]), "r"(ra[mi][1]), "r"(ra[mi][2]), "r"(ra[mi][3]),
                          "r"(rb[ni][0]), "r"(rb[ni][1]));
                }
        }
        __syncthreads();
    }

    // ---- epilogue ----
    #pragma unroll
    for (int mi = 0; mi < 4; mi++) {
        int row0 = tileM + wm*64 + mi*16 + g;   // rows row0, row0+8 (< T always)
        #pragma unroll
        for (int ni = 0; ni < 4; ni++) {
            int col = tileN + wn*32 + ni*8 + 2*t4;
            if (col >= N) continue;   // N always multiple of 8 -> frag-granular
            #pragma unroll
            for (int e = 0; e < 4; e++) {
                int r = row0 + (e >> 1) * 8;
                int c = col + (e & 1);
                float v = acc[mi][ni][e];
                size_t ci = (size_t)r * ldc + c;
                if (EPI == 1) {
                    C[ci] += v;
                } else if (EPI == 2) {
                    v += bias[c];
                    v = (v > 20.f) ? v : log1pf(expf(v));
                    C[ci] = v;
                } else {
                    C[ci] = v;
                }
            }
        }
    }
}

// ----------------------------------------------------------
__global__ void conv_silu_k(const float* __restrict__ xz,
                            const float* __restrict__ cw,
                            const float* __restrict__ cb,
                            float* __restrict__ xc)
{
    int idx = blockIdx.x * blockDim.x + threadIdx.x;
    if (idx >= TTOK * DINNER) return;
    int c = idx % DINNER;
    int t = idx / DINNER;
    int l = t % SEQ;

    float4 w4 = *(const float4*)(cw + c * 4);
    const size_t str = 2 * DINNER;
    float acc = cb[c];
    if (l >= 3) acc += w4.x * xz[(size_t)(t-3)*str + c];
    if (l >= 2) acc += w4.y * xz[(size_t)(t-2)*str + c];
    if (l >= 1) acc += w4.z * xz[(size_t)(t-1)*str + c];
    acc += w4.w * xz[(size_t)t*str + c];
    float s = 1.f / (1.f + expf(-acc));
    xc[idx] = acc * s;
}

// ----------------------------------------------------------
__global__ __launch_bounds__(256)
void scan_k(const float* __restrict__ xdbl,
            const float* __restrict__ dt,
            const float* __restrict__ xc,
            const float* __restrict__ xz,
            const float* __restrict__ A_log,
            const float* __restrict__ Dsk,
            float* __restrict__ y)
{
    int s = threadIdx.x & 15;
    int c = ((blockIdx.x & 127) << 4) + (threadIdx.x >> 4);
    int b = blockIdx.x >> 7;

    float A = -expf(A_log[(size_t)c * DSTATE + s]);
    float dval = Dsk[c];
    bool lane0 = (s == 0);
    float h = 0.f;

    int tbase = b * SEQ;
    for (int l = 0; l < SEQ; l++) {
        int t = tbase + l;
        float dtv = dt[(size_t)t * DINNER + c];
        float xv  = xc[(size_t)t * DINNER + c];
        float Bv  = xdbl[(size_t)t * XDBL_W + DTRANK + s];
        float Cv  = xdbl[(size_t)t * XDBL_W + DTRANK + DSTATE + s];

        float dA = __expf(dtv * A);
        h = dA * h + (dtv * xv) * Bv;
        float p = h * Cv;
        p += __shfl_xor_sync(0xffffffffu, p, 8);
        p += __shfl_xor_sync(0xffffffffu, p, 4);
        p += __shfl_xor_sync(0xffffffffu, p, 2);
        p += __shfl_xor_sync(0xffffffffu, p, 1);
        if (lane0) {
            float z = xz[(size_t)t * (2*DINNER) + DINNER + c];
            float sg = 1.f / (1.f + __expf(-z));
            y[(size_t)t * DINNER + c] = (p + dval * xv) * (z * sg);
        }
    }
}

// ----------------------------------------------------------
extern "C" void kernel_launch(void* const* d_in, const int* in_sizes, int n_in,
                              void* d_out, int out_size)
{
    const int*   tokens       = (const int*)  d_in[0];
    const float* embed        = (const float*)d_in[1];
    const float* norm_w       = (const float*)d_in[2];
    const float* in_proj_w    = (const float*)d_in[3];
    const float* conv_w       = (const float*)d_in[4];
    const float* conv_b       = (const float*)d_in[5];
    const float* x_proj_w     = (const float*)d_in[6];
    const float* dt_w         = (const float*)d_in[7];
    const float* dt_b         = (const float*)d_in[8];
    const float* A_log        = (const float*)d_in[9];
    const float* D_skip       = (const float*)d_in[10];
    const float* out_proj_w   = (const float*)d_in[11];
    const float* final_norm_w = (const float*)d_in[12];
    float* out = (float*)d_out;

    float *h, *xn, *xz, *xc, *xdbl, *dts, *y;
    cudaGetSymbolAddress((void**)&h,    g_h);
    cudaGetSymbolAddress((void**)&xn,   g_xn);
    cudaGetSymbolAddress((void**)&xz,   g_xz);
    cudaGetSymbolAddress((void**)&xc,   g_xc);
    cudaGetSymbolAddress((void**)&xdbl, g_xdbl);
    cudaGetSymbolAddress((void**)&dts,  g_dt);
    cudaGetSymbolAddress((void**)&y,    g_y);

    // opt-in smem (host-side attr set; not a stream op, capture-safe)
    cudaFuncSetAttribute(tf32gemm<0>, cudaFuncAttributeMaxDynamicSharedMemorySize, SMEM_BYTES);
    cudaFuncSetAttribute(tf32gemm<1>, cudaFuncAttributeMaxDynamicSharedMemorySize, SMEM_BYTES);
    cudaFuncSetAttribute(tf32gemm<2>, cudaFuncAttributeMaxDynamicSharedMemorySize, SMEM_BYTES);

    embed_k<<<TTOK, 256>>>(tokens, embed, h);

    for (int L = 0; L < NLAYER; L++) {
        rmsnorm_k<<<TTOK, 256>>>(h, norm_w + (size_t)L * DMODEL, xn);

        // in_proj: [2048,1024] x [4096,1024]^T -> [2048,4096]
        tf32gemm<0><<<dim3(2*DINNER/GBN, TTOK/GBM), 256, SMEM_BYTES>>>(
            xn, DMODEL,
            in_proj_w + (size_t)L * 2*DINNER*DMODEL, DMODEL,
            xz, 2*DINNER, nullptr, TTOK, 2*DINNER, DMODEL);

        conv_silu_k<<<(TTOK*DINNER + 255)/256, 256>>>(
            xz, conv_w + (size_t)L * DINNER*DCONV, conv_b + (size_t)L * DINNER, xc);

        // x_proj: [2048,2048] x [96,2048]^T -> [2048,96]
        tf32gemm<0><<<dim3(1, TTOK/GBM), 256, SMEM_BYTES>>>(
            xc, DINNER,
            x_proj_w + (size_t)L * XDBL_W*DINNER, DINNER,
            xdbl, XDBL_W, nullptr, TTOK, XDBL_W, DINNER);

        // dt: softplus([2048,96(:64)] x [2048,64]^T + dt_b)
        tf32gemm<2><<<dim3(DINNER/GBN, TTOK/GBM), 256, SMEM_BYTES>>>(
            xdbl, XDBL_W,
            dt_w + (size_t)L * DINNER*DTRANK, DTRANK,
            dts, DINNER, dt_b + (size_t)L * DINNER, TTOK, DINNER, DTRANK);

        scan_k<<<256, 256>>>(xdbl, dts, xc, xz,
                             A_log + (size_t)L * DINNER*DSTATE,
                             D_skip + (size_t)L * DINNER, y);

        // out_proj (+residual): [2048,2048] x [1024,2048]^T += h
        tf32gemm<1><<<dim3(DMODEL/GBN, TTOK/GBM), 256, SMEM_BYTES>>>(
            y, DINNER,
            out_proj_w + (size_t)L * DMODEL*DINNER, DINNER,
            h, DMODEL, nullptr, TTOK, DMODEL, DINNER);
    }

    rmsnorm_k<<<TTOK, 256>>>(h, final_norm_w, xn);

    // logits: [2048,1024] x [32000,1024]^T -> [2048,32000]
    tf32gemm<0><<<dim3(VOCAB/GBN, TTOK/GBM), 256, SMEM_BYTES>>>(
        xn, DMODEL, embed, DMODEL, out, VOCAB, nullptr, TTOK, VOCAB, DMODEL);
}

// round 4
// speedup vs baseline: 2.1719x; 1.0932x over previous
#include <cuda_runtime.h>
#include <math.h>
#include <stdint.h>

#define BATCH   2
#define SEQ     1024
#define DMODEL  1024
#define NLAYER  4
#define VOCAB   32000
#define DSTATE  16
#define DCONV   4
#define DINNER  2048
#define DTRANK  64
#define TTOK    (BATCH*SEQ)
#define XDBL_W  96

// -------- scratch (device globals: allocation-free) --------
__device__ float g_h   [TTOK*DMODEL];
__device__ float g_xn  [TTOK*DMODEL];
__device__ float g_xz  [TTOK*2*DINNER];
__device__ float g_xc  [TTOK*DINNER];
__device__ float g_xdbl[TTOK*XDBL_W];
__device__ float g_dt  [TTOK*DINNER];
__device__ float g_y   [TTOK*DINNER];
// tf32-pre-rounded weight copies
__device__ float g_w_in [NLAYER*2*DINNER*DMODEL];
__device__ float g_w_out[NLAYER*DMODEL*DINNER];
__device__ float g_w_xp [NLAYER*XDBL_W*DINNER];
__device__ float g_w_dt [NLAYER*DINNER*DTRANK];
__device__ float g_w_emb[VOCAB*DMODEL];

// ---------------- helpers ----------------
__device__ __forceinline__ float f2tf_f(float x) {
    uint32_t r;
    asm("cvt.rna.tf32.f32 %0, %1;" : "=r"(r) : "f"(x));
    return __uint_as_float(r);
}
__device__ __forceinline__ void cp16(uint32_t dst, const void* src, int srcBytes) {
    asm volatile("cp.async.cg.shared.global [%0], [%1], 16, %2;"
                 :: "r"(dst), "l"(src), "r"(srcBytes));
}
__device__ __forceinline__ void cp_commit() { asm volatile("cp.async.commit_group;"); }
template<int N> __device__ __forceinline__ void cp_wait() {
    asm volatile("cp.async.wait_group %0;" :: "n"(N));
}

// ---------------- elementwise kernels ----------------
__global__ void embed_k(const int* __restrict__ tok, const float* __restrict__ emb,
                        float* __restrict__ out)
{
    int t = blockIdx.x;
    int row = tok[t];
    ((float4*)(out + (size_t)t * DMODEL))[threadIdx.x] =
        ((const float4*)(emb + (size_t)row * DMODEL))[threadIdx.x];
}

__global__ void cvt_tf32_k(const float* __restrict__ s, float* __restrict__ d, int n4)
{
    int i = blockIdx.x * blockDim.x + threadIdx.x;
    if (i >= n4) return;
    float4 v = ((const float4*)s)[i];
    ((float4*)d)[i] = make_float4(f2tf_f(v.x), f2tf_f(v.y), f2tf_f(v.z), f2tf_f(v.w));
}

__global__ void rmsnorm_k(const float* __restrict__ x, const float* __restrict__ w,
                          float* __restrict__ out)
{
    int t = blockIdx.x;
    int tid = threadIdx.x;
    float4 v = ((const float4*)(x + (size_t)t * DMODEL))[tid];
    float ss = v.x*v.x + v.y*v.y + v.z*v.z + v.w*v.w;
    __shared__ float sbuf[8];
    #pragma unroll
    for (int o = 16; o; o >>= 1) ss += __shfl_xor_sync(0xffffffffu, ss, o);
    int warp = tid >> 5, lane = tid & 31;
    if (lane == 0) sbuf[warp] = ss;
    __syncthreads();
    if (warp == 0) {
        float s2 = (lane < 8) ? sbuf[lane] : 0.f;
        #pragma unroll
        for (int o = 4; o; o >>= 1) s2 += __shfl_xor_sync(0xffffffffu, s2, o);
        if (lane == 0) sbuf[0] = rsqrtf(s2 * (1.0f / DMODEL) + 1e-5f);
    }
    __syncthreads();
    float r = sbuf[0];
    float4 wv = ((const float4*)w)[tid];
    ((float4*)(out + (size_t)t * DMODEL))[tid] =
        make_float4(f2tf_f(v.x*r*wv.x), f2tf_f(v.y*r*wv.y),
                    f2tf_f(v.z*r*wv.z), f2tf_f(v.w*r*wv.w));
}

__global__ void conv_silu_k(const float* __restrict__ xz, const float* __restrict__ cw,
                            const float* __restrict__ cb, float* __restrict__ xc)
{
    int idx = blockIdx.x * blockDim.x + threadIdx.x;
    if (idx >= TTOK * DINNER) return;
    int c = idx % DINNER;
    int t = idx / DINNER;
    int l = t % SEQ;
    float4 w4 = *(const float4*)(cw + c * 4);
    const size_t str = 2 * DINNER;
    float acc = cb[c];
    if (l >= 3) acc += w4.x * xz[(size_t)(t-3)*str + c];
    if (l >= 2) acc += w4.y * xz[(size_t)(t-2)*str + c];
    if (l >= 1) acc += w4.z * xz[(size_t)(t-1)*str + c];
    acc += w4.w * xz[(size_t)t*str + c];
    float s = 1.f / (1.f + expf(-acc));
    xc[idx] = f2tf_f(acc * s);
}

__global__ __launch_bounds__(256)
void scan_k(const float* __restrict__ xdbl, const float* __restrict__ dt,
            const float* __restrict__ xc,   const float* __restrict__ xz,
            const float* __restrict__ A_log, const float* __restrict__ Dsk,
            float* __restrict__ y)
{
    int s = threadIdx.x & 15;
    int c = ((blockIdx.x & 127) << 4) + (threadIdx.x >> 4);
    int b = blockIdx.x >> 7;
    float A = -expf(A_log[(size_t)c * DSTATE + s]);
    float dval = Dsk[c];
    bool lane0 = (s == 0);
    float h = 0.f;
    int tbase = b * SEQ;
    for (int l = 0; l < SEQ; l++) {
        int t = tbase + l;
        float dtv = dt[(size_t)t * DINNER + c];
        float xv  = xc[(size_t)t * DINNER + c];
        float Bv  = xdbl[(size_t)t * XDBL_W + DTRANK + s];
        float Cv  = xdbl[(size_t)t * XDBL_W + DTRANK + DSTATE + s];
        float dA = __expf(dtv * A);
        h = dA * h + (dtv * xv) * Bv;
        float p = h * Cv;
        p += __shfl_xor_sync(0xffffffffu, p, 8);
        p += __shfl_xor_sync(0xffffffffu, p, 4);
        p += __shfl_xor_sync(0xffffffffu, p, 2);
        p += __shfl_xor_sync(0xffffffffu, p, 1);
        if (lane0) {
            float z = xz[(size_t)t * (2*DINNER) + DINNER + c];
            float sg = 1.f / (1.f + __expf(-z));
            y[(size_t)t * DINNER + c] = f2tf_f((p + dval * xv) * (z * sg));
        }
    }
}

// ----------------------------------------------------------
// TF32 mma.sync GEMM (NT): C[2048,N] = A[2048,K] x W[N,K]^T
// CTA 128xBN, 8 warps (2M x 4N), warp tile 64x(BN/4).
// Operands pre-rounded to tf32 -> NO cvt in mainloop.
// 4-stage cp.async pipeline, one __syncthreads per chunk.
// EPI: 0=store 1=accumulate 2=softplus(+bias) 3=store tf32-rounded
// ----------------------------------------------------------
#define KCH  32
#define PADK 36

template<int EPI, int BN>
__global__ __launch_bounds__(256, 1)
void mma_gemm(const float* __restrict__ A, int lda,
              const float* __restrict__ W, int ldw,
              float* __restrict__ C, int ldc,
              const float* __restrict__ bias,
              int N, int K)
{
    constexpr int NFR     = BN / 32;          // B fragments per warp per k-slice
    constexpr int STAGE_F = (128 + BN) * PADK;
    constexpr int NTASK   = (128 + BN) * 8;   // float4 loads per chunk

    extern __shared__ float smemf[];
    uint32_t sb = (uint32_t)__cvta_generic_to_shared(smemf);

    int tid = threadIdx.x, lane = tid & 31, warp = tid >> 5;
    int wm = warp & 1;            // 0..1 : 64-row half
    int wn = warp >> 1;           // 0..3 : (BN/4)-col quarter
    int g  = lane >> 2;           // 0..7
    int t4 = lane & 3;            // 0..3
    int tileM = blockIdx.y * 128, tileN = blockIdx.x * BN;

    float acc[4][NFR][4];
    #pragma unroll
    for (int mi = 0; mi < 4; mi++)
        #pragma unroll
        for (int ni = 0; ni < NFR; ni++)
            #pragma unroll
            for (int e = 0; e < 4; e++) acc[mi][ni][e] = 0.f;

    const int iters = K / KCH;

    auto load_chunk = [&](int s, int it) {
        int k0 = it * KCH;
        uint32_t sbase = sb + (uint32_t)(s * STAGE_F * 4);
        #pragma unroll
        for (int i = 0; i < NTASK/256; i++) {
            int task = tid + i * 256;
            int row = task >> 3;
            int c4  = (task & 7) * 4;
            uint32_t dst = sbase + (uint32_t)((row * PADK + c4) * 4);
            if (row < 128) {
                cp16(dst, A + (size_t)(tileM + row) * lda + k0 + c4, 16);
            } else {
                int wr = tileN + (row - 128);
                const float* src = W + (size_t)(wr < N ? wr : 0) * ldw + k0 + c4;
                cp16(dst, src, wr < N ? 16 : 0);
            }
        }
        cp_commit();
    };

    int npro = iters < 3 ? iters : 3;
    for (int c = 0; c < npro; c++) load_chunk(c, c);

    for (int it = 0; it < iters; it++) {
        int s = it & 3;
        int rem = iters - 1 - it;
        if (rem >= 2)      cp_wait<2>();
        else if (rem == 1) cp_wait<1>();
        else               cp_wait<0>();
        __syncthreads();

        const float* As = smemf + s*STAGE_F + (wm*64)*PADK;
        const float* Bs = smemf + s*STAGE_F + (128 + wn*(BN/4))*PADK;

        #pragma unroll
        for (int ks = 0; ks < 4; ks++) {
            uint32_t ra[4][4], rb[NFR][2];
            #pragma unroll
            for (int mi = 0; mi < 4; mi++) {
                const float* ap = As + (mi*16 + g)*PADK + ks*8 + t4;
                ra[mi][0] = __float_as_uint(ap[0]);
                ra[mi][1] = __float_as_uint(ap[8*PADK]);
                ra[mi][2] = __float_as_uint(ap[4]);
                ra[mi][3] = __float_as_uint(ap[8*PADK + 4]);
            }
            #pragma unroll
            for (int ni = 0; ni < NFR; ni++) {
                const float* bp = Bs + (ni*8 + g)*PADK + ks*8 + t4;
                rb[ni][0] = __float_as_uint(bp[0]);
                rb[ni][1] = __float_as_uint(bp[4]);
            }
            #pragma unroll
            for (int mi = 0; mi < 4; mi++)
                #pragma unroll
                for (int ni = 0; ni < NFR; ni++) {
                    asm volatile(
                        "mma.sync.aligned.m16n8k8.row.col.f32.tf32.tf32.f32 "
                        "{%0,%1,%2,%3}, {%4,%5,%6,%7}, {%8,%9}, {%0,%1,%2,%3};\n"
                        : "+f"(acc[mi][ni][0]), "+f"(acc[mi][ni][1]),
                          "+f"(acc[mi][ni][2]), "+f"(acc[mi][ni][3])
                        : "r"(ra[mi][0]), "r"(ra[mi][1]), "r"(ra[mi][2]), "r"(ra[mi][3]),
                          "r"(rb[ni][0]), "r"(rb[ni][1]));
                }
        }
        if (it + 3 < iters) load_chunk((it + 3) & 3, it + 3);
    }

    // ---- epilogue: float2 stores ----
    int warpN0 = tileN + wn*(BN/4);
    #pragma unroll
    for (int mi = 0; mi < 4; mi++) {
        int r0 = tileM + wm*64 + mi*16 + g;
        #pragma unroll
        for (int ni = 0; ni < NFR; ni++) {
            int c = warpN0 + ni*8 + 2*t4;
            if (c >= N) continue;
            float2 v0 = make_float2(acc[mi][ni][0], acc[mi][ni][1]);
            float2 v1 = make_float2(acc[mi][ni][2], acc[mi][ni][3]);
            float* p0 = C + (size_t)r0 * ldc + c;
            float* p1 = C + (size_t)(r0 + 8) * ldc + c;
            if (EPI == 1) {
                float2 o0 = *(float2*)p0, o1 = *(float2*)p1;
                v0.x += o0.x; v0.y += o0.y; v1.x += o1.x; v1.y += o1.y;
            } else if (EPI == 2) {
                float b0 = bias[c], b1 = bias[c+1];
                v0.x += b0; v0.y += b1; v1.x += b0; v1.y += b1;
                v0.x = (v0.x > 20.f) ? v0.x : log1pf(expf(v0.x));
                v0.y = (v0.y > 20.f) ? v0.y : log1pf(expf(v0.y));
                v1.x = (v1.x > 20.f) ? v1.x : log1pf(expf(v1.x));
                v1.y = (v1.y > 20.f) ? v1.y : log1pf(expf(v1.y));
            } else if (EPI == 3) {
                v0.x = f2tf_f(v0.x); v0.y = f2tf_f(v0.y);
                v1.x = f2tf_f(v1.x); v1.y = f2tf_f(v1.y);
            }
            *(float2*)p0 = v0;
            *(float2*)p1 = v1;
        }
    }
}

#define SMEMB(BN) ((128 + BN) * PADK * 4 * 4)   // 4 stages

// ----------------------------------------------------------
extern "C" void kernel_launch(void* const* d_in, const int* in_sizes, int n_in,
                              void* d_out, int out_size)
{
    const int*   tokens       = (const int*)  d_in[0];
    const float* embed        = (const float*)d_in[1];
    const float* norm_w       = (const float*)d_in[2];
    const float* in_proj_w    = (const float*)d_in[3];
    const float* conv_w       = (const float*)d_in[4];
    const float* conv_b       = (const float*)d_in[5];
    const float* x_proj_w     = (const float*)d_in[6];
    const float* dt_w         = (const float*)d_in[7];
    const float* dt_b         = (const float*)d_in[8];
    const float* A_log        = (const float*)d_in[9];
    const float* D_skip       = (const float*)d_in[10];
    const float* out_proj_w   = (const float*)d_in[11];
    const float* final_norm_w = (const float*)d_in[12];
    float* out = (float*)d_out;

    float *h, *xn, *xz, *xc, *xdbl, *dts, *y;
    float *w_in, *w_out, *w_xp, *w_dt, *w_emb;
    cudaGetSymbolAddress((void**)&h,    g_h);
    cudaGetSymbolAddress((void**)&xn,   g_xn);
    cudaGetSymbolAddress((void**)&xz,   g_xz);
    cudaGetSymbolAddress((void**)&xc,   g_xc);
    cudaGetSymbolAddress((void**)&xdbl, g_xdbl);
    cudaGetSymbolAddress((void**)&dts,  g_dt);
    cudaGetSymbolAddress((void**)&y,    g_y);
    cudaGetSymbolAddress((void**)&w_in,  g_w_in);
    cudaGetSymbolAddress((void**)&w_out, g_w_out);
    cudaGetSymbolAddress((void**)&w_xp,  g_w_xp);
    cudaGetSymbolAddress((void**)&w_dt,  g_w_dt);
    cudaGetSymbolAddress((void**)&w_emb, g_w_emb);

    cudaFuncSetAttribute(mma_gemm<0,256>, cudaFuncAttributeMaxDynamicSharedMemorySize, SMEMB(256));
    cudaFuncSetAttribute(mma_gemm<1,128>, cudaFuncAttributeMaxDynamicSharedMemorySize, SMEMB(128));
    cudaFuncSetAttribute(mma_gemm<2,128>, cudaFuncAttributeMaxDynamicSharedMemorySize, SMEMB(128));
    cudaFuncSetAttribute(mma_gemm<3,128>, cudaFuncAttributeMaxDynamicSharedMemorySize, SMEMB(128));

    // one-pass tf32 pre-rounding of all GEMM weight operands
    {
        int n4;
        n4 = NLAYER*2*DINNER*DMODEL/4; cvt_tf32_k<<<(n4+255)/256, 256>>>(in_proj_w,  w_in,  n4);
        n4 = NLAYER*DMODEL*DINNER/4;   cvt_tf32_k<<<(n4+255)/256, 256>>>(out_proj_w, w_out, n4);
        n4 = NLAYER*XDBL_W*DINNER/4;   cvt_tf32_k<<<(n4+255)/256, 256>>>(x_proj_w,   w_xp,  n4);
        n4 = NLAYER*DINNER*DTRANK/4;   cvt_tf32_k<<<(n4+255)/256, 256>>>(dt_w,       w_dt,  n4);
        n4 = VOCAB*DMODEL/4;           cvt_tf32_k<<<(n4+255)/256, 256>>>(embed,      w_emb, n4);
    }

    embed_k<<<TTOK, 256>>>(tokens, embed, h);

    for (int L = 0; L < NLAYER; L++) {
        rmsnorm_k<<<TTOK, 256>>>(h, norm_w + (size_t)L * DMODEL, xn);

        // in_proj: [2048,1024] x [4096,1024]^T -> xz
        mma_gemm<0,256><<<dim3(2*DINNER/256, TTOK/128), 256, SMEMB(256)>>>(
            xn, DMODEL, w_in + (size_t)L * 2*DINNER*DMODEL, DMODEL,
            xz, 2*DINNER, nullptr, 2*DINNER, DMODEL);

        conv_silu_k<<<(TTOK*DINNER + 255)/256, 256>>>(
            xz, conv_w + (size_t)L * DINNER*DCONV, conv_b + (size_t)L * DINNER, xc);

        // x_proj: [2048,2048] x [96,2048]^T -> xdbl (tf32-rounded output)
        mma_gemm<3,128><<<dim3(1, TTOK/128), 256, SMEMB(128)>>>(
            xc, DINNER, w_xp + (size_t)L * XDBL_W*DINNER, DINNER,
            xdbl, XDBL_W, nullptr, XDBL_W, DINNER);

        // dt: softplus([2048,96(:64)] x [2048,64]^T + dt_b)
        mma_gemm<2,128><<<dim3(DINNER/128, TTOK/128), 256, SMEMB(128)>>>(
            xdbl, XDBL_W, w_dt + (size_t)L * DINNER*DTRANK, DTRANK,
            dts, DINNER, dt_b + (size_t)L * DINNER, DINNER, DTRANK);

        scan_k<<<256, 256>>>(xdbl, dts, xc, xz,
                             A_log + (size_t)L * DINNER*DSTATE,
                             D_skip + (size_t)L * DINNER, y);

        // out_proj (+residual): [2048,2048] x [1024,2048]^T += h
        mma_gemm<1,128><<<dim3(DMODEL/128, TTOK/128), 256, SMEMB(128)>>>(
            y, DINNER, w_out + (size_t)L * DMODEL*DINNER, DINNER,
            h, DMODEL, nullptr, DMODEL, DINNER);
    }

    rmsnorm_k<<<TTOK, 256>>>(h, final_norm_w, xn);

    // logits: [2048,1024] x [32000,1024]^T
    mma_gemm<0,256><<<dim3(VOCAB/256, TTOK/128), 256, SMEMB(256)>>>(
        xn, DMODEL, w_emb, DMODEL, out, VOCAB, nullptr, VOCAB, DMODEL);
}